// round 6
// baseline (speedup 1.0000x reference)
#include <cuda_runtime.h>
#include <cstdint>
#include <math.h>

#define DEVI __device__ __forceinline__

static constexpr int BN = 16384, FAN = 16, BE = BN * FAN, EMB = 128, HID = 256;

// ---- device scratch (static; no allocations allowed) ----
__device__ __align__(16) float g_relb2[16 * HID];
__device__ __align__(16) float g_neigh[BN * HID];
__device__ __align__(16) float g_Bw [16 * 256 * 32];  // k_events B: tf32, permuted+swizzled smem image
__device__ __align__(16) float g_Bw2[12 * 256 * 32];  // k_final  B: same

DEVI uint32_t smaddr(const void* p) {
    uint32_t a;
    asm("{ .reg .u64 t; cvta.to.shared.u64 t, %1; cvt.u32.u64 %0, t; }" : "=r"(a) : "l"(p));
    return a;
}
DEVI void cpa16(uint32_t d, const void* s) {
    asm volatile("cp.async.ca.shared.global [%0], [%1], 16;" :: "r"(d), "l"(s));
}
#define CP_COMMIT() asm volatile("cp.async.commit_group;")
#define CP_WAIT(n)  asm volatile("cp.async.wait_group %0;" :: "n"(n))

DEVI uint32_t tf32u(float x) {
    uint32_t u;
    asm("cvt.rna.tf32.f32 %0, %1;" : "=r"(u) : "f"(x));
    return u;
}
DEVI float tf32f(float x) { return __uint_as_float(tf32u(x)); }

DEVI void lds64(uint32_t& x, uint32_t& y, uint32_t a) {
    asm volatile("ld.shared.v2.b32 {%0,%1}, [%2];" : "=r"(x), "=r"(y) : "r"(a));
}
DEVI void mma8(float* c, const uint32_t* a, uint32_t b0, uint32_t b1) {
    asm volatile(
        "mma.sync.aligned.m16n8k8.row.col.f32.tf32.tf32.f32 "
        "{%0,%1,%2,%3}, {%4,%5,%6,%7}, {%8,%9}, {%0,%1,%2,%3};"
        : "+f"(c[0]), "+f"(c[1]), "+f"(c[2]), "+f"(c[3])
        : "r"(a[0]), "r"(a[1]), "r"(a[2]), "r"(a[3]), "r"(b0), "r"(b1));
}

static constexpr int LD   = 36;        // A smem row stride (floats), padded
static constexpr int A_F  = 128 * LD;  // 4608 floats / A stage
static constexpr int B2_F = 256 * 32;  // 8192 floats / B stage (dense 128B rows)

// ---- B staging: logical W[r][k] (k within 32-chunk) -> smem-image position ----
DEVI void stash(float* dst, int r, int k, float v) {
    int kg = k >> 3, j = k & 7;
    int pos = kg * 8 + 2 * (j & 3) + (j >> 2);
    int cc  = (pos >> 2) ^ ((r & 3) << 1);
    dst[r * 32 + cc * 4 + (pos & 3)] = __uint_as_float(tf32u(v));
}

// ---- one K=32 chunk; CTA 128x256, 8 warps (2x4), warp tile 64x64 ----
// A consumed as raw fp32 bits (tf32 HW truncation); B image pre-rounded (rna).
DEVI void mma_chunk(const float* As, uint32_t bB, int wm, int wn, int g, int t,
                    float (&acc)[4][8][4]) {
    const uint32_t sw = (uint32_t)((g & 3) << 1);
    uint32_t nbase[8];
#pragma unroll
    for (int nt = 0; nt < 8; nt++)
        nbase[nt] = bB + (uint32_t)((wn * 64 + nt * 8 + g) * 128) + ((t & 1) << 3);
#pragma unroll
    for (int ks = 0; ks < 4; ks++) {
        uint32_t a[4][4];
#pragma unroll
        for (int mt = 0; mt < 4; mt++) {
            const float* r0 = As + (wm * 64 + mt * 16 + g) * LD + ks * 8;
            const float* r8 = r0 + 8 * LD;
            a[mt][0] = __float_as_uint(r0[t]);
            a[mt][1] = __float_as_uint(r8[t]);
            a[mt][2] = __float_as_uint(r0[t + 4]);
            a[mt][3] = __float_as_uint(r8[t + 4]);
        }
        const uint32_t cc = (((uint32_t)(ks * 2 + (t >> 1))) ^ sw) << 4;
#pragma unroll
        for (int nt = 0; nt < 8; nt++) {
            uint32_t b0, b1;
            lds64(b0, b1, nbase[nt] + cc);
#pragma unroll
            for (int mt = 0; mt < 4; mt++)
                mma8(acc[mt][nt], a[mt], b0, b1);
        }
    }
}

// ---------------- kernel 0: stage weights (tf32 + permute + swizzle) ----------------
__global__ void k_prep(const float* __restrict__ Ws, const float* __restrict__ Wd,
                       const float* __restrict__ W2, const float* __restrict__ Wself,
                       const float* __restrict__ Wneigh) {
    int flat = blockIdx.x * 256 + threadIdx.x;
    if (flat < 16 * 8192) {
        int chunk = flat >> 13, r = (flat >> 5) & 255, k = flat & 31;
        float v;
        if (chunk < 4)      v = Ws[r * 128 + chunk * 32 + k];
        else if (chunk < 8) v = Wd[r * 128 + (chunk - 4) * 32 + k];
        else                v = W2[r * 256 + (chunk - 8) * 32 + k];
        stash(g_Bw + chunk * 8192, r, k, v);
    } else {
        int f = flat - 16 * 8192;
        int chunk = f >> 13, r = (f >> 5) & 255, k = f & 31;
        float v = (chunk < 4) ? Wself[r * 128 + chunk * 32 + k]
                              : Wneigh[r * 256 + (chunk - 4) * 32 + k];
        stash(g_Bw2 + chunk * 8192, r, k, v);
    }
}

// ---------------- kernel 1: relb2[r][j] = b2[j] + edge_emb[r] . edge_lin_w[j] ----------------
__global__ void k_relproj(const float* __restrict__ eemb, const float* __restrict__ We,
                          const float* __restrict__ b2) {
    int r = blockIdx.x, j = threadIdx.x;
    const float4* e = (const float4*)(eemb + r * EMB);
    const float4* w = (const float4*)(We + (long)j * EMB);
    float acc = b2[j];
#pragma unroll
    for (int k = 0; k < EMB / 4; k++) {
        float4 a = e[k], b = w[k];
        acc += a.x * b.x + a.y * b.y + a.z * b.z + a.w * b.w;
    }
    g_relb2[r * HID + j] = acc;
}

// ---------------- kernel 2: event GEMM [BE,512]x[512,256] -> mask/relu -> mean ----------------
extern __shared__ float smf[];

__global__ void __launch_bounds__(256) k_events(
    const int* __restrict__ nbr_ev, const int* __restrict__ ev_st,
    const int* __restrict__ ev_dt, const int* __restrict__ ev_et,
    const int* __restrict__ ev_sid, const int* __restrict__ ev_did,
    const int* __restrict__ ev_ts, const float* __restrict__ ev_w,
    const float* __restrict__ emb0, const float* __restrict__ emb1,
    const float* __restrict__ w1, const float* __restrict__ b1v)
{
    float* Bsb  = smf;                       // 3 x B2_F
    float* Asb  = smf + 3 * B2_F;            // 3 x A_F
    float* meta = smf + 3 * B2_F + 3 * A_F;
    const float** srcP = (const float**)meta;           // 128 ptrs (256 f)
    const float** dstP = (const float**)(meta + 256);   // 128 ptrs
    int*   relA = (int*)(meta + 512);
    float* vmA  = meta + 640;
    float* tsA  = meta + 768;
    float* wlA  = meta + 896;
    float* rb   = meta + 1024;                          // 16x256
    float2* w1s = (float2*)(meta + 5120);               // 256
    float* b1s  = meta + 5632;                          // 256

    const int tid = threadIdx.x;
    const int wid = tid >> 5, lane = tid & 31;
    const int wm = wid >> 2, wn = wid & 3;               // warp grid 2 x 4
    const int g = lane >> 2, t = lane & 3;

    if (tid < 128) {
        int e   = blockIdx.x * 128 + tid;
        int raw = nbr_ev[e];
        int v   = raw >= 0;
        int ev  = v ? raw : 0;
        long sid = ev_sid[ev], did = ev_did[ev];
        srcP[tid] = (ev_st[ev] == 0 ? emb0 : emb1) + sid * EMB;
        dstP[tid] = (ev_dt[ev] == 0 ? emb0 : emb1) + did * EMB;
        relA[tid] = ev_et[ev];
        vmA[tid]  = v ? 1.0f : 0.0f;
        tsA[tid]  = (float)ev_ts[ev] / 1000000.0f;
        wlA[tid]  = log1pf(ev_w[ev]);
    }
#pragma unroll
    for (int i = 0; i < 16; i++) rb[tid + i * 256] = g_relb2[tid + i * 256];
    w1s[tid] = make_float2(w1[tid * 2], w1[tid * 2 + 1]);
    b1s[tid] = b1v[tid];
    __syncthreads();

    uint32_t bU[3]; float* Asp[3]; uint32_t aU[3];
#pragma unroll
    for (int s = 0; s < 3; s++) {
        bU[s]  = smaddr(Bsb + s * B2_F);
        Asp[s] = Asb + s * A_F;
        aU[s]  = smaddr(Asp[s]);
    }

    auto load_chunk = [&](int kc, int s) {
        // B: staged smem image, linear copy (8192 floats)
#pragma unroll
        for (int i = 0; i < 8; i++) {
            int task = tid + i * 256;
            cpa16(bU[s] + (uint32_t)task * 16u, g_Bw + (size_t)kc * 8192 + task * 4);
        }
        if (kc < 8) {  // A: gathered src/dst embeddings (1024 16B tasks)
#pragma unroll
            for (int i = 0; i < 4; i++) {
                int task = tid + i * 256, row = task >> 3, seg = task & 7;
                const float* p = (kc < 4 ? srcP[row] : dstP[row]) + (kc & 3) * 32;
                cpa16(aU[s] + (uint32_t)((row * LD + seg * 4) * 4), p + seg * 4);
            }
        } else {       // A: a1 = relu(feat @ W1^T + b1), rna-rounded at store
            float* A = Asp[s];
#pragma unroll
            for (int i = 0; i < 16; i++) {
                int task = tid + i * 256, e = task >> 5, c = task & 31;
                int j = (kc - 8) * 32 + c;
                float2 wv = w1s[j];
                A[e * LD + c] = tf32f(fmaxf(tsA[e] * wv.x + wlA[e] * wv.y + b1s[j], 0.0f));
            }
        }
    };

    float acc[4][8][4];
#pragma unroll
    for (int mt = 0; mt < 4; mt++)
#pragma unroll
        for (int nt = 0; nt < 8; nt++)
#pragma unroll
            for (int r = 0; r < 4; r++) acc[mt][nt][r] = 0.0f;

    load_chunk(0, 0); CP_COMMIT();
    load_chunk(1, 1); CP_COMMIT();
    for (int kc = 0; kc < 16; kc++) {
        int s = kc % 3;
        if (kc == 15) { CP_WAIT(0); } else { CP_WAIT(1); }
        __syncthreads();
        if (kc < 14) { load_chunk(kc + 2, (kc + 2) % 3); CP_COMMIT(); }
        mma_chunk(Asp[s], bU[s], wm, wn, g, t, acc);
    }

    // epilogue: +relb2[rel], relu, mask, mean over each 16-row node group
#pragma unroll
    for (int mt = 0; mt < 4; mt++) {
        int eg = wm * 64 + mt * 16 + g, eg8 = eg + 8;
        float vg = vmA[eg], vg8 = vmA[eg8];
        const float* rbg  = rb + relA[eg] * 256;
        const float* rbg8 = rb + relA[eg8] * 256;
        int node = blockIdx.x * 8 + wm * 4 + mt;
#pragma unroll
        for (int nt = 0; nt < 8; nt++) {
            int col = wn * 64 + nt * 8 + t * 2;
            float s0 = fmaxf(acc[mt][nt][0] + rbg[col], 0.0f) * vg
                     + fmaxf(acc[mt][nt][2] + rbg8[col], 0.0f) * vg8;
            float s1 = fmaxf(acc[mt][nt][1] + rbg[col + 1], 0.0f) * vg
                     + fmaxf(acc[mt][nt][3] + rbg8[col + 1], 0.0f) * vg8;
            s0 += __shfl_xor_sync(0xFFFFFFFFu, s0, 4);
            s0 += __shfl_xor_sync(0xFFFFFFFFu, s0, 8);
            s0 += __shfl_xor_sync(0xFFFFFFFFu, s0, 16);
            s1 += __shfl_xor_sync(0xFFFFFFFFu, s1, 4);
            s1 += __shfl_xor_sync(0xFFFFFFFFu, s1, 8);
            s1 += __shfl_xor_sync(0xFFFFFFFFu, s1, 16);
            if (g == 0)
                *(float2*)(g_neigh + node * 256 + col) =
                    make_float2(s0 * 0.0625f, s1 * 0.0625f);
        }
    }
}

// ---------------- kernel 3: out = relu(self_e @ Wself^T + neigh @ Wneigh^T) ----------------
__global__ void __launch_bounds__(256) k_final(
    const int* __restrict__ node_ids, const float* __restrict__ emb0,
    float* __restrict__ out)
{
    float* Bsb  = smf;
    float* Asb  = smf + 3 * B2_F;
    float* meta = smf + 3 * B2_F + 3 * A_F;
    const float** selfP = (const float**)meta;  // 128 ptrs

    const int tid = threadIdx.x;
    const int wid = tid >> 5, lane = tid & 31;
    const int wm = wid >> 2, wn = wid & 3;
    const int g = lane >> 2, t = lane & 3;

    if (tid < 128) {
        long nid = node_ids[blockIdx.x * 128 + tid];
        selfP[tid] = emb0 + nid * EMB;
    }
    __syncthreads();

    uint32_t bU[3]; float* Asp[3]; uint32_t aU[3];
#pragma unroll
    for (int s = 0; s < 3; s++) {
        bU[s]  = smaddr(Bsb + s * B2_F);
        Asp[s] = Asb + s * A_F;
        aU[s]  = smaddr(Asp[s]);
    }

    auto load_chunk = [&](int kc, int s) {
#pragma unroll
        for (int i = 0; i < 8; i++) {
            int task = tid + i * 256;
            cpa16(bU[s] + (uint32_t)task * 16u, g_Bw2 + (size_t)kc * 8192 + task * 4);
        }
#pragma unroll
        for (int i = 0; i < 4; i++) {
            int task = tid + i * 256, row = task >> 3, seg = task & 7;
            const float* p;
            if (kc < 4) p = selfP[row] + kc * 32;
            else        p = g_neigh + (long)(blockIdx.x * 128 + row) * 256 + (kc - 4) * 32;
            cpa16(aU[s] + (uint32_t)((row * LD + seg * 4) * 4), p + seg * 4);
        }
    };

    float acc[4][8][4];
#pragma unroll
    for (int mt = 0; mt < 4; mt++)
#pragma unroll
        for (int nt = 0; nt < 8; nt++)
#pragma unroll
            for (int r = 0; r < 4; r++) acc[mt][nt][r] = 0.0f;

    load_chunk(0, 0); CP_COMMIT();
    load_chunk(1, 1); CP_COMMIT();
    for (int kc = 0; kc < 12; kc++) {
        int s = kc % 3;
        if (kc == 11) { CP_WAIT(0); } else { CP_WAIT(1); }
        __syncthreads();
        if (kc < 10) { load_chunk(kc + 2, (kc + 2) % 3); CP_COMMIT(); }
        mma_chunk(Asp[s], bU[s], wm, wn, g, t, acc);
    }

#pragma unroll
    for (int mt = 0; mt < 4; mt++) {
        int row0 = blockIdx.x * 128 + wm * 64 + mt * 16;
#pragma unroll
        for (int nt = 0; nt < 8; nt++) {
            int col = wn * 64 + nt * 8 + t * 2;
            *(float2*)(out + (long)(row0 + g) * 256 + col) =
                make_float2(fmaxf(acc[mt][nt][0], 0.0f), fmaxf(acc[mt][nt][1], 0.0f));
            *(float2*)(out + (long)(row0 + g + 8) * 256 + col) =
                make_float2(fmaxf(acc[mt][nt][2], 0.0f), fmaxf(acc[mt][nt][3], 0.0f));
        }
    }
}

static constexpr int SMEM2 = (3 * B2_F + 3 * A_F + 5888) * 4;  // 177152 B
static constexpr int SMEM3 = (3 * B2_F + 3 * A_F + 256) * 4;   // 154624 B

extern "C" void kernel_launch(void* const* d_in, const int* in_sizes, int n_in,
                              void* d_out, int out_size) {
    const int*   node_ids = (const int*)d_in[0];
    const int*   nbr_ev   = (const int*)d_in[1];
    const int*   ev_st    = (const int*)d_in[2];
    const int*   ev_dt    = (const int*)d_in[3];
    const int*   ev_et    = (const int*)d_in[4];
    const int*   ev_sid   = (const int*)d_in[5];
    const int*   ev_did   = (const int*)d_in[6];
    const int*   ev_ts    = (const int*)d_in[7];
    const float* ev_w     = (const float*)d_in[8];
    const float* emb0     = (const float*)d_in[9];
    const float* emb1     = (const float*)d_in[10];
    const float* edge_emb = (const float*)d_in[11];
    const float* edge_lin = (const float*)d_in[12];
    const float* mlp_w1   = (const float*)d_in[13];
    const float* mlp_b1   = (const float*)d_in[14];
    const float* mlp_w2   = (const float*)d_in[15];
    const float* mlp_b2   = (const float*)d_in[16];
    const float* ev_src_w = (const float*)d_in[17];
    const float* ev_dst_w = (const float*)d_in[18];
    const float* self_w   = (const float*)d_in[19];
    const float* neigh_w  = (const float*)d_in[20];
    float* out = (float*)d_out;

    cudaFuncSetAttribute(k_events, cudaFuncAttributeMaxDynamicSharedMemorySize, SMEM2);
    cudaFuncSetAttribute(k_final,  cudaFuncAttributeMaxDynamicSharedMemorySize, SMEM3);

    k_prep<<<896, 256>>>(ev_src_w, ev_dst_w, mlp_w2, self_w, neigh_w);
    k_relproj<<<16, 256>>>(edge_emb, edge_lin, mlp_b2);
    k_events<<<BE / 128, 256, SMEM2>>>(nbr_ev, ev_st, ev_dt, ev_et, ev_sid, ev_did,
                                       ev_ts, ev_w, emb0, emb1, mlp_w1, mlp_b1);
    k_final<<<BN / 128, 256, SMEM3>>>(node_ids, emb0, out);
}

// round 7
// speedup vs baseline: 1.3933x; 1.3933x over previous
#include <cuda_runtime.h>
#include <cuda_fp16.h>
#include <cstdint>
#include <math.h>

#define DEVI __device__ __forceinline__

static constexpr int BN = 16384, FAN = 16, BE = BN * FAN, EMB = 128, HID = 256;

// ---- device scratch (static; no allocations allowed) ----
__device__ __align__(16) float  g_relb2[16 * HID];
__device__ __align__(16) __half g_neighh[BN * HID];        // fp16, pair-permuted per 64-col block
__device__ __align__(16) __half g_Bwh [8 * 256 * 64];      // k_events B: fp16 swizzled smem image
__device__ __align__(16) __half g_Bw2h[6 * 256 * 64];      // k_final  B: same

DEVI uint32_t smaddr(const void* p) {
    uint32_t a;
    asm("{ .reg .u64 t; cvta.to.shared.u64 t, %1; cvt.u32.u64 %0, t; }" : "=r"(a) : "l"(p));
    return a;
}
DEVI void cpa16(uint32_t d, const void* s) {
    asm volatile("cp.async.ca.shared.global [%0], [%1], 16;" :: "r"(d), "l"(s));
}
#define CP_COMMIT() asm volatile("cp.async.commit_group;")
#define CP_WAIT(n)  asm volatile("cp.async.wait_group %0;" :: "n"(n))

DEVI void lds64(uint32_t& x, uint32_t& y, uint32_t a) {
    asm volatile("ld.shared.v2.b32 {%0,%1}, [%2];" : "=r"(x), "=r"(y) : "r"(a));
}
DEVI void sts128(uint32_t a, uint32_t x, uint32_t y, uint32_t z, uint32_t w) {
    asm volatile("st.shared.v4.b32 [%0], {%1,%2,%3,%4};" :: "r"(a), "r"(x), "r"(y), "r"(z), "r"(w) : "memory");
}
DEVI uint32_t h2u(__half2 h) { return *(uint32_t*)&h; }

// fp16 m16n8k16, fp32 accumulate
DEVI void mma16(float* c, const uint32_t* a, uint32_t b0, uint32_t b1) {
    asm volatile(
        "mma.sync.aligned.m16n8k16.row.col.f32.f16.f16.f32 "
        "{%0,%1,%2,%3}, {%4,%5,%6,%7}, {%8,%9}, {%0,%1,%2,%3};"
        : "+f"(c[0]), "+f"(c[1]), "+f"(c[2]), "+f"(c[3])
        : "r"(a[0]), "r"(a[1]), "r"(a[2]), "r"(a[3]), "r"(b0), "r"(b1));
}

// ---- fp16 smem image: row r (128B = 64 half = K64), kstep ks (16 half), pair j (0..7) ----
// pair permutation p = 2*(j&3) + (j>>2)  puts {j=t, j=t+4} into one 8B slot -> LDS.64 = {lo,hi} regs
// row swizzle: 8B slot s -> s ^ ((r&3)<<2)   (32B-granular, conflict-free per 16-lane phase)
DEVI void stashh(__half* dst, int r, int k, float v) {
    int q = k >> 1, ks = q >> 3, j = q & 7;
    int p = 2 * (j & 3) + (j >> 2);
    int s8 = (ks * 4 + (p >> 1)) ^ ((r & 3) << 2);
    dst[r * 64 + s8 * 4 + (p & 1) * 2 + (k & 1)] = __float2half_rn(v);
}

static constexpr int A_BYT  = 128 * 128;          // A stage: 128 rows x 128B
static constexpr int B_BYT  = 256 * 128;          // B stage: 256 rows x 128B
static constexpr int STG    = A_BYT + B_BYT;      // 49152
static constexpr int CH_BYT = 256 * 64 * 2;       // one B chunk image = 32768 B

// ---- one K=64 chunk; CTA 128x256, 16 warps (4x4), warp tile 32x64 ----
DEVI void mma_chunk(uint32_t aB, uint32_t bB, int wm, int wn, int g, int t,
                    float (&acc)[2][8][4]) {
    const uint32_t asw = ((uint32_t)(g & 3)) << 2;
    const uint32_t arow = aB + (uint32_t)((wm * 32 + g) * 128);
    uint32_t brow[8];
#pragma unroll
    for (int nt = 0; nt < 8; nt++)
        brow[nt] = bB + (uint32_t)((wn * 64 + nt * 8 + g) * 128);
#pragma unroll
    for (int ks = 0; ks < 4; ks++) {
        const uint32_t soff = ((((uint32_t)(ks * 4 + t)) ^ asw) << 3);
        uint32_t a[2][4];
#pragma unroll
        for (int mt = 0; mt < 2; mt++) {
            lds64(a[mt][0], a[mt][2], arow + mt * 2048 + soff);           // row g   : {a0,a2}
            lds64(a[mt][1], a[mt][3], arow + mt * 2048 + 1024 + soff);    // row g+8 : {a1,a3}
        }
#pragma unroll
        for (int nt = 0; nt < 8; nt++) {
            uint32_t b0, b1;
            lds64(b0, b1, brow[nt] + soff);
            mma16(acc[0][nt], a[0], b0, b1);
            mma16(acc[1][nt], a[1], b0, b1);
        }
    }
}

// ---------------- kernel 0: stage weights (fp16 rn + permute + swizzle) ----------------
__global__ void k_prep(const float* __restrict__ Ws, const float* __restrict__ Wd,
                       const float* __restrict__ W2, const float* __restrict__ Wself,
                       const float* __restrict__ Wneigh) {
    int flat = blockIdx.x * 256 + threadIdx.x;
    if (flat < 8 * 16384) {
        int chunk = flat >> 14, r = (flat >> 6) & 255, k = flat & 63;
        float v;
        if (chunk < 2)      v = Ws[r * 128 + chunk * 64 + k];
        else if (chunk < 4) v = Wd[r * 128 + (chunk - 2) * 64 + k];
        else                v = W2[r * 256 + (chunk - 4) * 64 + k];
        stashh(g_Bwh + chunk * 16384, r, k, v);
    } else {
        int f = flat - 8 * 16384;
        int chunk = f >> 14, r = (f >> 6) & 255, k = f & 63;
        float v = (chunk < 2) ? Wself[r * 128 + chunk * 64 + k]
                              : Wneigh[r * 256 + (chunk - 2) * 64 + k];
        stashh(g_Bw2h + chunk * 16384, r, k, v);
    }
}

// ---------------- kernel 1: relb2[r][j] = b2[j] + edge_emb[r] . edge_lin_w[j] ----------------
__global__ void k_relproj(const float* __restrict__ eemb, const float* __restrict__ We,
                          const float* __restrict__ b2) {
    int r = blockIdx.x, j = threadIdx.x;
    const float4* e = (const float4*)(eemb + r * EMB);
    const float4* w = (const float4*)(We + (long)j * EMB);
    float acc = b2[j];
#pragma unroll
    for (int k = 0; k < EMB / 4; k++) {
        float4 a = e[k], b = w[k];
        acc += a.x * b.x + a.y * b.y + a.z * b.z + a.w * b.w;
    }
    g_relb2[r * HID + j] = acc;
}

extern __shared__ float smf[];

// meta float indices (stages occupy first 3*STG bytes = 36864 floats)
static constexpr int MI   = 3 * STG / 4;   // 36864
static constexpr int MI_SRCP = MI;          // 128 ptrs (256 f)
static constexpr int MI_DSTP = MI + 256;
static constexpr int MI_REL  = MI + 512;    // 128 int
static constexpr int MI_VM   = MI + 640;
static constexpr int MI_TS   = MI + 768;
static constexpr int MI_WL   = MI + 896;
static constexpr int MI_W1   = MI + 1024;   // 256 float2 (512 f)
static constexpr int MI_B1   = MI + 1536;   // 256 f
static constexpr int MI_RB   = MI + 1792;   // 16 x 256
static constexpr int SMEM_EV = (MI_RB + 4096) * 4;   // 171008 B
static constexpr int SMEM_FI = (MI + 256) * 4;       // 148480 B

// fill one emb-derived A kstep: thread owns (row = tid>>2, ks = tid&3)
DEVI void fill_emb_kstep(uint32_t aB, const float* src, int row, int ks) {
    float4 f[4];
#pragma unroll
    for (int q = 0; q < 4; q++) f[q] = ((const float4*)src)[q];
    uint32_t h[8];
#pragma unroll
    for (int p = 0; p < 8; p++) {
        int j = (p >> 1) + ((p & 1) << 2);
        float x = (j & 1) ? f[j >> 1].z : f[j >> 1].x;
        float y = (j & 1) ? f[j >> 1].w : f[j >> 1].y;
        h[p] = h2u(__floats2half2_rn(x, y));
    }
    uint32_t dest = aB + (uint32_t)(row * 128) + (((uint32_t)(ks * 4) ^ ((row & 3) << 2)) << 3);
    sts128(dest, h[0], h[1], h[2], h[3]);
    sts128(dest + 16, h[4], h[5], h[6], h[7]);
}

// ---------------- kernel 2: event GEMM [BE,512]x[512,256] fp16 -> mask/relu -> mean ----------------
__global__ void __launch_bounds__(512) k_events(
    const int* __restrict__ nbr_ev, const int* __restrict__ ev_st,
    const int* __restrict__ ev_dt, const int* __restrict__ ev_et,
    const int* __restrict__ ev_sid, const int* __restrict__ ev_did,
    const int* __restrict__ ev_ts, const float* __restrict__ ev_w,
    const float* __restrict__ emb0, const float* __restrict__ emb1,
    const float* __restrict__ w1, const float* __restrict__ b1v)
{
    const uint32_t smb = smaddr(smf);
    const float** srcP = (const float**)(smf + MI_SRCP);
    const float** dstP = (const float**)(smf + MI_DSTP);
    int*    relA = (int*)(smf + MI_REL);
    float*  vmA  = smf + MI_VM;
    float*  tsA  = smf + MI_TS;
    float*  wlA  = smf + MI_WL;
    float2* w1s  = (float2*)(smf + MI_W1);
    float*  b1s  = smf + MI_B1;
    float*  rb   = smf + MI_RB;

    const int tid = threadIdx.x;
    const int wid = tid >> 5, lane = tid & 31;
    const int wm = wid >> 2, wn = wid & 3;    // 4x4 warp grid
    const int g = lane >> 2, t = lane & 3;

    if (tid < 128) {
        int e   = blockIdx.x * 128 + tid;
        int raw = nbr_ev[e];
        int v   = raw >= 0;
        int ev  = v ? raw : 0;
        long sid = ev_sid[ev], did = ev_did[ev];
        srcP[tid] = (ev_st[ev] == 0 ? emb0 : emb1) + sid * EMB;
        dstP[tid] = (ev_dt[ev] == 0 ? emb0 : emb1) + did * EMB;
        relA[tid] = ev_et[ev];
        vmA[tid]  = v ? 1.0f : 0.0f;
        tsA[tid]  = (float)ev_ts[ev] / 1000000.0f;
        wlA[tid]  = log1pf(ev_w[ev]);
    }
#pragma unroll
    for (int i = 0; i < 8; i++) rb[tid + i * 512] = g_relb2[tid + i * 512];
    if (tid < 256) {
        w1s[tid] = make_float2(w1[tid * 2], w1[tid * 2 + 1]);
        b1s[tid] = b1v[tid];
    }
    __syncthreads();

    const int frow = tid >> 2, fks = tid & 3;   // A-fill task

    auto load_chunk = [&](int kc, int s) {
        const uint32_t base = smb + (uint32_t)(s * STG);
        // B: pre-swizzled image, linear 16B copy (2048 tasks)
#pragma unroll
        for (int i = 0; i < 4; i++) {
            int task = tid + i * 512;
            cpa16(base + (uint32_t)A_BYT + (uint32_t)task * 16u,
                  (const char*)g_Bwh + (size_t)kc * CH_BYT + task * 16);
        }
        if (kc < 4) {           // gathered embeddings: LDG f32 -> half2 -> STS
            const float* src = (kc < 2 ? srcP[frow] : dstP[frow]) + ((kc & 1) << 6) + fks * 16;
            fill_emb_kstep(base, src, frow, fks);
        } else {                // a1 = relu(feat @ W1^T + b1) straight to half2
            int cb = ((kc - 4) << 6) + fks * 16;
            float tsv = tsA[frow], wlv = wlA[frow];
            uint32_t h[8];
#pragma unroll
            for (int p = 0; p < 8; p++) {
                int j = (p >> 1) + ((p & 1) << 2);
                int c0 = cb + 2 * j;
                float2 wa = w1s[c0], wb = w1s[c0 + 1];
                float v0 = fmaxf(tsv * wa.x + wlv * wa.y + b1s[c0], 0.0f);
                float v1 = fmaxf(tsv * wb.x + wlv * wb.y + b1s[c0 + 1], 0.0f);
                h[p] = h2u(__floats2half2_rn(v0, v1));
            }
            uint32_t dest = base + (uint32_t)(frow * 128)
                          + (((uint32_t)(fks * 4) ^ ((frow & 3) << 2)) << 3);
            sts128(dest, h[0], h[1], h[2], h[3]);
            sts128(dest + 16, h[4], h[5], h[6], h[7]);
        }
    };

    float acc[2][8][4];
#pragma unroll
    for (int mt = 0; mt < 2; mt++)
#pragma unroll
        for (int nt = 0; nt < 8; nt++)
#pragma unroll
            for (int r = 0; r < 4; r++) acc[mt][nt][r] = 0.0f;

    load_chunk(0, 0); CP_COMMIT();
    load_chunk(1, 1); CP_COMMIT();
    for (int kc = 0; kc < 8; kc++) {
        int s = kc % 3;
        if (kc == 7) { CP_WAIT(0); } else { CP_WAIT(1); }
        __syncthreads();
        if (kc < 6) { load_chunk(kc + 2, (kc + 2) % 3); CP_COMMIT(); }
        mma_chunk(smb + (uint32_t)(s * STG), smb + (uint32_t)(s * STG + A_BYT),
                  wm, wn, g, t, acc);
    }

    // epilogue: +relb2[rel], relu, mask, mean(16) -> g_neighh (fp16, permuted layout)
#pragma unroll
    for (int mt = 0; mt < 2; mt++) {
        int eg = wm * 32 + mt * 16 + g, eg8 = eg + 8;
        float vg = vmA[eg], vg8 = vmA[eg8];
        const float* rbg  = rb + relA[eg] * 256;
        const float* rbg8 = rb + relA[eg8] * 256;
        int node = blockIdx.x * 8 + wm * 2 + mt;
#pragma unroll
        for (int nt = 0; nt < 8; nt++) {
            int col = wn * 64 + nt * 8 + t * 2;
            float s0 = fmaxf(acc[mt][nt][0] + rbg[col], 0.0f) * vg
                     + fmaxf(acc[mt][nt][2] + rbg8[col], 0.0f) * vg8;
            float s1 = fmaxf(acc[mt][nt][1] + rbg[col + 1], 0.0f) * vg
                     + fmaxf(acc[mt][nt][3] + rbg8[col + 1], 0.0f) * vg8;
            s0 += __shfl_xor_sync(0xFFFFFFFFu, s0, 4);
            s0 += __shfl_xor_sync(0xFFFFFFFFu, s0, 8);
            s0 += __shfl_xor_sync(0xFFFFFFFFu, s0, 16);
            s1 += __shfl_xor_sync(0xFFFFFFFFu, s1, 4);
            s1 += __shfl_xor_sync(0xFFFFFFFFu, s1, 8);
            s1 += __shfl_xor_sync(0xFFFFFFFFu, s1, 16);
            if (g == 0) {
                // permuted fp16 layout: chunk=wn, ks=nt>>1, p=2t+(nt&1)
                int idx = node * 256 + wn * 64 + (nt >> 1) * 16 + (2 * t + (nt & 1)) * 2;
                *(__half2*)(g_neighh + idx) =
                    __floats2half2_rn(s0 * 0.0625f, s1 * 0.0625f);
            }
        }
    }
}

// ---------------- kernel 3: out = relu(self_e @ Wself^T + neigh @ Wneigh^T) ----------------
__global__ void __launch_bounds__(512) k_final(
    const int* __restrict__ node_ids, const float* __restrict__ emb0,
    float* __restrict__ out)
{
    const uint32_t smb = smaddr(smf);
    const float** selfP = (const float**)(smf + MI);

    const int tid = threadIdx.x;
    const int wid = tid >> 5, lane = tid & 31;
    const int wm = wid >> 2, wn = wid & 3;
    const int g = lane >> 2, t = lane & 3;

    if (tid < 128) {
        long nid = node_ids[blockIdx.x * 128 + tid];
        selfP[tid] = emb0 + nid * EMB;
    }
    __syncthreads();

    const int frow = tid >> 2, fks = tid & 3;

    auto load_chunk = [&](int kc, int s) {
        const uint32_t base = smb + (uint32_t)(s * STG);
#pragma unroll
        for (int i = 0; i < 4; i++) {
            int task = tid + i * 512;
            cpa16(base + (uint32_t)A_BYT + (uint32_t)task * 16u,
                  (const char*)g_Bw2h + (size_t)kc * CH_BYT + task * 16);
        }
        if (kc < 2) {           // self emb f32 -> half2
            const float* src = selfP[frow] + (kc << 6) + fks * 16;
            fill_emb_kstep(base, src, frow, fks);
        } else {                // neigh: fp16 pre-permuted -> cp.async with dest swizzle
#pragma unroll
            for (int i = 0; i < 2; i++) {
                int task = tid + i * 512, row = task >> 3, c = task & 7;
                const __half* src = g_neighh + (size_t)(blockIdx.x * 128 + row) * 256
                                  + ((kc - 2) << 6) + c * 8;
                uint32_t dest = base + (uint32_t)(row * 128)
                              + (((uint32_t)c ^ ((row & 3) << 1)) << 4);
                cpa16(dest, src);
            }
        }
    };

    float acc[2][8][4];
#pragma unroll
    for (int mt = 0; mt < 2; mt++)
#pragma unroll
        for (int nt = 0; nt < 8; nt++)
#pragma unroll
            for (int r = 0; r < 4; r++) acc[mt][nt][r] = 0.0f;

    load_chunk(0, 0); CP_COMMIT();
    load_chunk(1, 1); CP_COMMIT();
    for (int kc = 0; kc < 6; kc++) {
        int s = kc % 3;
        if (kc == 5) { CP_WAIT(0); } else { CP_WAIT(1); }
        __syncthreads();
        if (kc < 4) { load_chunk(kc + 2, (kc + 2) % 3); CP_COMMIT(); }
        mma_chunk(smb + (uint32_t)(s * STG), smb + (uint32_t)(s * STG + A_BYT),
                  wm, wn, g, t, acc);
    }

#pragma unroll
    for (int mt = 0; mt < 2; mt++) {
        int row0 = blockIdx.x * 128 + wm * 32 + mt * 16;
#pragma unroll
        for (int nt = 0; nt < 8; nt++) {
            int col = wn * 64 + nt * 8 + t * 2;
            *(float2*)(out + (long)(row0 + g) * 256 + col) =
                make_float2(fmaxf(acc[mt][nt][0], 0.0f), fmaxf(acc[mt][nt][1], 0.0f));
            *(float2*)(out + (long)(row0 + g + 8) * 256 + col) =
                make_float2(fmaxf(acc[mt][nt][2], 0.0f), fmaxf(acc[mt][nt][3], 0.0f));
        }
    }
}

extern "C" void kernel_launch(void* const* d_in, const int* in_sizes, int n_in,
                              void* d_out, int out_size) {
    const int*   node_ids = (const int*)d_in[0];
    const int*   nbr_ev   = (const int*)d_in[1];
    const int*   ev_st    = (const int*)d_in[2];
    const int*   ev_dt    = (const int*)d_in[3];
    const int*   ev_et    = (const int*)d_in[4];
    const int*   ev_sid   = (const int*)d_in[5];
    const int*   ev_did   = (const int*)d_in[6];
    const int*   ev_ts    = (const int*)d_in[7];
    const float* ev_w     = (const float*)d_in[8];
    const float* emb0     = (const float*)d_in[9];
    const float* emb1     = (const float*)d_in[10];
    const float* edge_emb = (const float*)d_in[11];
    const float* edge_lin = (const float*)d_in[12];
    const float* mlp_w1   = (const float*)d_in[13];
    const float* mlp_b1   = (const float*)d_in[14];
    const float* mlp_w2   = (const float*)d_in[15];
    const float* mlp_b2   = (const float*)d_in[16];
    const float* ev_src_w = (const float*)d_in[17];
    const float* ev_dst_w = (const float*)d_in[18];
    const float* self_w   = (const float*)d_in[19];
    const float* neigh_w  = (const float*)d_in[20];
    float* out = (float*)d_out;

    cudaFuncSetAttribute(k_events, cudaFuncAttributeMaxDynamicSharedMemorySize, SMEM_EV);
    cudaFuncSetAttribute(k_final,  cudaFuncAttributeMaxDynamicSharedMemorySize, SMEM_FI);

    k_prep<<<896, 256>>>(ev_src_w, ev_dst_w, mlp_w2, self_w, neigh_w);
    k_relproj<<<16, 256>>>(edge_emb, edge_lin, mlp_b2);
    k_events<<<BE / 128, 512, SMEM_EV>>>(nbr_ev, ev_st, ev_dt, ev_et, ev_sid, ev_did,
                                         ev_ts, ev_w, emb0, emb1, mlp_w1, mlp_b1);
    k_final<<<BN / 128, 512, SMEM_FI>>>(node_ids, emb0, out);
}

// round 8
// speedup vs baseline: 1.3987x; 1.0039x over previous
#include <cuda_runtime.h>
#include <cuda_fp16.h>
#include <cstdint>
#include <math.h>

#define DEVI __device__ __forceinline__

static constexpr int BN = 16384, FAN = 16, BE = BN * FAN, EMB = 128, HID = 256;

// ---- device scratch (static; no allocations allowed) ----
__device__ __align__(16) float  g_relb2[16 * HID];
__device__ __align__(16) __half g_neighh[BN * HID];        // fp16, pair-permuted per 64-col block
__device__ __align__(16) __half g_Bwh [8 * 256 * 64];      // k_events B: fp16 swizzled smem image
__device__ __align__(16) __half g_Bw2h[6 * 256 * 64];      // k_final  B: same

DEVI uint32_t smaddr(const void* p) {
    uint32_t a;
    asm("{ .reg .u64 t; cvta.to.shared.u64 t, %1; cvt.u32.u64 %0, t; }" : "=r"(a) : "l"(p));
    return a;
}
DEVI void cpa16(uint32_t d, const void* s) {
    asm volatile("cp.async.ca.shared.global [%0], [%1], 16;" :: "r"(d), "l"(s));
}
#define CP_COMMIT() asm volatile("cp.async.commit_group;")
#define CP_WAIT(n)  asm volatile("cp.async.wait_group %0;" :: "n"(n))

DEVI void lds64(uint32_t& x, uint32_t& y, uint32_t a) {
    asm volatile("ld.shared.v2.b32 {%0,%1}, [%2];" : "=r"(x), "=r"(y) : "r"(a));
}
DEVI void sts128(uint32_t a, uint32_t x, uint32_t y, uint32_t z, uint32_t w) {
    asm volatile("st.shared.v4.b32 [%0], {%1,%2,%3,%4};" :: "r"(a), "r"(x), "r"(y), "r"(z), "r"(w) : "memory");
}
DEVI uint32_t h2u(__half2 h) { return *(uint32_t*)&h; }

// fp16 m16n8k16, fp32 accumulate
DEVI void mma16(float* c, const uint32_t* a, uint32_t b0, uint32_t b1) {
    asm volatile(
        "mma.sync.aligned.m16n8k16.row.col.f32.f16.f16.f32 "
        "{%0,%1,%2,%3}, {%4,%5,%6,%7}, {%8,%9}, {%0,%1,%2,%3};"
        : "+f"(c[0]), "+f"(c[1]), "+f"(c[2]), "+f"(c[3])
        : "r"(a[0]), "r"(a[1]), "r"(a[2]), "r"(a[3]), "r"(b0), "r"(b1));
}

// ---- fp16 smem image: row r (128B = 64 half = K64), kstep ks (16 half), pair j (0..7) ----
// pair permutation p = 2*(j&3) + (j>>2)  puts {j=t, j=t+4} into one 8B slot -> LDS.64 = {lo,hi} regs
// row swizzle: 8B slot s -> s ^ ((r&3)<<2)   (32B-granular, conflict-free per 16-lane phase)
DEVI void stashh(__half* dst, int r, int k, float v) {
    int q = k >> 1, ks = q >> 3, j = q & 7;
    int p = 2 * (j & 3) + (j >> 2);
    int s8 = (ks * 4 + (p >> 1)) ^ ((r & 3) << 2);
    dst[r * 64 + s8 * 4 + (p & 1) * 2 + (k & 1)] = __float2half_rn(v);
}

static constexpr int A_BYT  = 128 * 128;          // A stage: 128 rows x 128B
static constexpr int B_BYT  = 256 * 128;          // B stage: 256 rows x 128B
static constexpr int STG    = A_BYT + B_BYT;      // 49152
static constexpr int CH_BYT = 256 * 64 * 2;       // one B chunk image = 32768 B

// ---- per-kstep fragment load (12 x LDS.64) ----
DEVI void frag_load(uint32_t arow, uint32_t brow0, uint32_t asw, int t, int ks,
                    uint32_t (&a)[2][4], uint32_t (&b)[8][2]) {
    const uint32_t soff = ((((uint32_t)(ks * 4 + t)) ^ asw) << 3);
#pragma unroll
    for (int mt = 0; mt < 2; mt++) {
        lds64(a[mt][0], a[mt][2], arow + (uint32_t)(mt * 2048) + soff);         // row g
        lds64(a[mt][1], a[mt][3], arow + (uint32_t)(mt * 2048 + 1024) + soff);  // row g+8
    }
#pragma unroll
    for (int nt = 0; nt < 8; nt++)
        lds64(b[nt][0], b[nt][1], brow0 + (uint32_t)(nt * 1024) + soff);
}

// ---- one K=64 chunk; CTA 128x256, 16 warps (4x4), warp tile 32x64 ----
// Software-pipelined ksteps: fragments for ks+1 load while MMAs of ks issue.
DEVI void mma_chunk(uint32_t aB, uint32_t bB, int wm, int wn, int g, int t,
                    float (&acc)[2][8][4]) {
    const uint32_t asw = ((uint32_t)(g & 3)) << 2;
    const uint32_t arow  = aB + (uint32_t)((wm * 32 + g) * 128);
    const uint32_t brow0 = bB + (uint32_t)((wn * 64 + g) * 128);   // swizzle invariant in nt (row&3==g&3)

    uint32_t a[2][2][4], b[2][8][2];
    frag_load(arow, brow0, asw, t, 0, a[0], b[0]);
#pragma unroll
    for (int ks = 0; ks < 4; ks++) {
        const int cur = ks & 1;
        if (ks < 3)
            frag_load(arow, brow0, asw, t, ks + 1, a[cur ^ 1], b[cur ^ 1]);
#pragma unroll
        for (int nt = 0; nt < 8; nt++) {
            mma16(acc[0][nt], a[cur][0], b[cur][nt][0], b[cur][nt][1]);
            mma16(acc[1][nt], a[cur][1], b[cur][nt][0], b[cur][nt][1]);
        }
    }
}

// ---------------- kernel 0: stage weights (fp16 rn + permute + swizzle) ----------------
__global__ void k_prep(const float* __restrict__ Ws, const float* __restrict__ Wd,
                       const float* __restrict__ W2, const float* __restrict__ Wself,
                       const float* __restrict__ Wneigh) {
    int flat = blockIdx.x * 256 + threadIdx.x;
    if (flat < 8 * 16384) {
        int chunk = flat >> 14, r = (flat >> 6) & 255, k = flat & 63;
        float v;
        if (chunk < 2)      v = Ws[r * 128 + chunk * 64 + k];
        else if (chunk < 4) v = Wd[r * 128 + (chunk - 2) * 64 + k];
        else                v = W2[r * 256 + (chunk - 4) * 64 + k];
        stashh(g_Bwh + chunk * 16384, r, k, v);
    } else {
        int f = flat - 8 * 16384;
        int chunk = f >> 14, r = (f >> 6) & 255, k = f & 63;
        float v = (chunk < 2) ? Wself[r * 128 + chunk * 64 + k]
                              : Wneigh[r * 256 + (chunk - 2) * 64 + k];
        stashh(g_Bw2h + chunk * 16384, r, k, v);
    }
}

// ---------------- kernel 1: relb2[r][j] = b2[j] + edge_emb[r] . edge_lin_w[j] ----------------
__global__ void k_relproj(const float* __restrict__ eemb, const float* __restrict__ We,
                          const float* __restrict__ b2) {
    int r = blockIdx.x, j = threadIdx.x;
    const float4* e = (const float4*)(eemb + r * EMB);
    const float4* w = (const float4*)(We + (long)j * EMB);
    float acc = b2[j];
#pragma unroll
    for (int k = 0; k < EMB / 4; k++) {
        float4 a = e[k], b = w[k];
        acc += a.x * b.x + a.y * b.y + a.z * b.z + a.w * b.w;
    }
    g_relb2[r * HID + j] = acc;
}

extern __shared__ float smf[];

// meta float indices (stages occupy first 3*STG bytes = 36864 floats)
static constexpr int MI   = 3 * STG / 4;   // 36864
static constexpr int MI_SRCP = MI;          // 128 ptrs (256 f)
static constexpr int MI_DSTP = MI + 256;
static constexpr int MI_REL  = MI + 512;    // 128 int
static constexpr int MI_VM   = MI + 640;
static constexpr int MI_TS   = MI + 768;
static constexpr int MI_WL   = MI + 896;
static constexpr int MI_W1   = MI + 1024;   // 256 float2 (512 f)
static constexpr int MI_B1   = MI + 1536;   // 256 f
static constexpr int MI_RB   = MI + 1792;   // 16 x 256
static constexpr int SMEM_EV = (MI_RB + 4096) * 4;   // 171008 B
static constexpr int SMEM_FI = (MI + 256) * 4;       // 148480 B

// fill one emb-derived A kstep: thread owns (row = tid>>2, ks = tid&3)
DEVI void fill_emb_kstep(uint32_t aB, const float* src, int row, int ks) {
    float4 f[4];
#pragma unroll
    for (int q = 0; q < 4; q++) f[q] = ((const float4*)src)[q];
    uint32_t h[8];
#pragma unroll
    for (int p = 0; p < 8; p++) {
        int j = (p >> 1) + ((p & 1) << 2);
        float x = (j & 1) ? f[j >> 1].z : f[j >> 1].x;
        float y = (j & 1) ? f[j >> 1].w : f[j >> 1].y;
        h[p] = h2u(__floats2half2_rn(x, y));
    }
    uint32_t dest = aB + (uint32_t)(row * 128) + (((uint32_t)(ks * 4) ^ ((row & 3) << 2)) << 3);
    sts128(dest, h[0], h[1], h[2], h[3]);
    sts128(dest + 16, h[4], h[5], h[6], h[7]);
}

// ---------------- kernel 2: event GEMM [BE,512]x[512,256] fp16 -> mask/relu -> mean ----------------
__global__ void __launch_bounds__(512) k_events(
    const int* __restrict__ nbr_ev, const int* __restrict__ ev_st,
    const int* __restrict__ ev_dt, const int* __restrict__ ev_et,
    const int* __restrict__ ev_sid, const int* __restrict__ ev_did,
    const int* __restrict__ ev_ts, const float* __restrict__ ev_w,
    const float* __restrict__ emb0, const float* __restrict__ emb1,
    const float* __restrict__ w1, const float* __restrict__ b1v)
{
    const uint32_t smb = smaddr(smf);
    const float** srcP = (const float**)(smf + MI_SRCP);
    const float** dstP = (const float**)(smf + MI_DSTP);
    int*    relA = (int*)(smf + MI_REL);
    float*  vmA  = smf + MI_VM;
    float*  tsA  = smf + MI_TS;
    float*  wlA  = smf + MI_WL;
    float2* w1s  = (float2*)(smf + MI_W1);
    float*  b1s  = smf + MI_B1;
    float*  rb   = smf + MI_RB;

    const int tid = threadIdx.x;
    const int wid = tid >> 5, lane = tid & 31;
    const int wm = wid >> 2, wn = wid & 3;    // 4x4 warp grid
    const int g = lane >> 2, t = lane & 3;

    if (tid < 128) {
        int e   = blockIdx.x * 128 + tid;
        int raw = nbr_ev[e];
        int v   = raw >= 0;
        int ev  = v ? raw : 0;
        long sid = ev_sid[ev], did = ev_did[ev];
        srcP[tid] = (ev_st[ev] == 0 ? emb0 : emb1) + sid * EMB;
        dstP[tid] = (ev_dt[ev] == 0 ? emb0 : emb1) + did * EMB;
        relA[tid] = ev_et[ev];
        vmA[tid]  = v ? 1.0f : 0.0f;
        tsA[tid]  = (float)ev_ts[ev] / 1000000.0f;
        wlA[tid]  = log1pf(ev_w[ev]);
    }
#pragma unroll
    for (int i = 0; i < 8; i++) rb[tid + i * 512] = g_relb2[tid + i * 512];
    if (tid < 256) {
        w1s[tid] = make_float2(w1[tid * 2], w1[tid * 2 + 1]);
        b1s[tid] = b1v[tid];
    }
    __syncthreads();

    const int frow = tid >> 2, fks = tid & 3;   // A-fill task

    auto load_chunk = [&](int kc, int s) {
        const uint32_t base = smb + (uint32_t)(s * STG);
        // B: pre-swizzled image, linear 16B copy (2048 tasks)
#pragma unroll
        for (int i = 0; i < 4; i++) {
            int task = tid + i * 512;
            cpa16(base + (uint32_t)A_BYT + (uint32_t)task * 16u,
                  (const char*)g_Bwh + (size_t)kc * CH_BYT + task * 16);
        }
        if (kc < 4) {           // gathered embeddings: LDG f32 -> half2 -> STS
            const float* src = (kc < 2 ? srcP[frow] : dstP[frow]) + ((kc & 1) << 6) + fks * 16;
            fill_emb_kstep(base, src, frow, fks);
        } else {                // a1 = relu(feat @ W1^T + b1) straight to half2
            int cb = ((kc - 4) << 6) + fks * 16;
            float tsv = tsA[frow], wlv = wlA[frow];
            uint32_t h[8];
#pragma unroll
            for (int p = 0; p < 8; p++) {
                int j = (p >> 1) + ((p & 1) << 2);
                int c0 = cb + 2 * j;
                float2 wa = w1s[c0], wb = w1s[c0 + 1];
                float v0 = fmaxf(tsv * wa.x + wlv * wa.y + b1s[c0], 0.0f);
                float v1 = fmaxf(tsv * wb.x + wlv * wb.y + b1s[c0 + 1], 0.0f);
                h[p] = h2u(__floats2half2_rn(v0, v1));
            }
            uint32_t dest = base + (uint32_t)(frow * 128)
                          + (((uint32_t)(fks * 4) ^ ((frow & 3) << 2)) << 3);
            sts128(dest, h[0], h[1], h[2], h[3]);
            sts128(dest + 16, h[4], h[5], h[6], h[7]);
        }
    };

    float acc[2][8][4];
#pragma unroll
    for (int mt = 0; mt < 2; mt++)
#pragma unroll
        for (int nt = 0; nt < 8; nt++)
#pragma unroll
            for (int r = 0; r < 4; r++) acc[mt][nt][r] = 0.0f;

    load_chunk(0, 0); CP_COMMIT();
    load_chunk(1, 1); CP_COMMIT();
    for (int kc = 0; kc < 8; kc++) {
        int s = kc % 3;
        if (kc == 7) { CP_WAIT(0); } else { CP_WAIT(1); }
        __syncthreads();
        if (kc < 6) { load_chunk(kc + 2, (kc + 2) % 3); CP_COMMIT(); }
        mma_chunk(smb + (uint32_t)(s * STG), smb + (uint32_t)(s * STG + A_BYT),
                  wm, wn, g, t, acc);
    }

    // epilogue: +relb2[rel], relu, mask, mean(16) -> g_neighh (fp16, permuted layout)
#pragma unroll
    for (int mt = 0; mt < 2; mt++) {
        int eg = wm * 32 + mt * 16 + g, eg8 = eg + 8;
        float vg = vmA[eg], vg8 = vmA[eg8];
        const float* rbg  = rb + relA[eg] * 256;
        const float* rbg8 = rb + relA[eg8] * 256;
        int node = blockIdx.x * 8 + wm * 2 + mt;
#pragma unroll
        for (int nt = 0; nt < 8; nt++) {
            int col = wn * 64 + nt * 8 + t * 2;
            float s0 = fmaxf(acc[mt][nt][0] + rbg[col], 0.0f) * vg
                     + fmaxf(acc[mt][nt][2] + rbg8[col], 0.0f) * vg8;
            float s1 = fmaxf(acc[mt][nt][1] + rbg[col + 1], 0.0f) * vg
                     + fmaxf(acc[mt][nt][3] + rbg8[col + 1], 0.0f) * vg8;
            s0 += __shfl_xor_sync(0xFFFFFFFFu, s0, 4);
            s0 += __shfl_xor_sync(0xFFFFFFFFu, s0, 8);
            s0 += __shfl_xor_sync(0xFFFFFFFFu, s0, 16);
            s1 += __shfl_xor_sync(0xFFFFFFFFu, s1, 4);
            s1 += __shfl_xor_sync(0xFFFFFFFFu, s1, 8);
            s1 += __shfl_xor_sync(0xFFFFFFFFu, s1, 16);
            if (g == 0) {
                // permuted fp16 layout: chunk=wn, ks=nt>>1, p=2t+(nt&1)
                int idx = node * 256 + wn * 64 + (nt >> 1) * 16 + (2 * t + (nt & 1)) * 2;
                *(__half2*)(g_neighh + idx) =
                    __floats2half2_rn(s0 * 0.0625f, s1 * 0.0625f);
            }
        }
    }
}

// ---------------- kernel 3: out = relu(self_e @ Wself^T + neigh @ Wneigh^T) ----------------
__global__ void __launch_bounds__(512) k_final(
    const int* __restrict__ node_ids, const float* __restrict__ emb0,
    float* __restrict__ out)
{
    const uint32_t smb = smaddr(smf);
    const float** selfP = (const float**)(smf + MI);

    const int tid = threadIdx.x;
    const int wid = tid >> 5, lane = tid & 31;
    const int wm = wid >> 2, wn = wid & 3;
    const int g = lane >> 2, t = lane & 3;

    if (tid < 128) {
        long nid = node_ids[blockIdx.x * 128 + tid];
        selfP[tid] = emb0 + nid * EMB;
    }
    __syncthreads();

    const int frow = tid >> 2, fks = tid & 3;

    auto load_chunk = [&](int kc, int s) {
        const uint32_t base = smb + (uint32_t)(s * STG);
#pragma unroll
        for (int i = 0; i < 4; i++) {
            int task = tid + i * 512;
            cpa16(base + (uint32_t)A_BYT + (uint32_t)task * 16u,
                  (const char*)g_Bw2h + (size_t)kc * CH_BYT + task * 16);
        }
        if (kc < 2) {           // self emb f32 -> half2
            const float* src = selfP[frow] + (kc << 6) + fks * 16;
            fill_emb_kstep(base, src, frow, fks);
        } else {                // neigh: fp16 pre-permuted -> cp.async with dest swizzle
#pragma unroll
            for (int i = 0; i < 2; i++) {
                int task = tid + i * 512, row = task >> 3, c = task & 7;
                const __half* src = g_neighh + (size_t)(blockIdx.x * 128 + row) * 256
                                  + ((kc - 2) << 6) + c * 8;
                uint32_t dest = base + (uint32_t)(row * 128)
                              + (((uint32_t)c ^ ((row & 3) << 1)) << 4);
                cpa16(dest, src);
            }
        }
    };

    float acc[2][8][4];
#pragma unroll
    for (int mt = 0; mt < 2; mt++)
#pragma unroll
        for (int nt = 0; nt < 8; nt++)
#pragma unroll
            for (int r = 0; r < 4; r++) acc[mt][nt][r] = 0.0f;

    load_chunk(0, 0); CP_COMMIT();
    load_chunk(1, 1); CP_COMMIT();
    for (int kc = 0; kc < 6; kc++) {
        int s = kc % 3;
        if (kc == 5) { CP_WAIT(0); } else { CP_WAIT(1); }
        __syncthreads();
        if (kc < 4) { load_chunk(kc + 2, (kc + 2) % 3); CP_COMMIT(); }
        mma_chunk(smb + (uint32_t)(s * STG), smb + (uint32_t)(s * STG + A_BYT),
                  wm, wn, g, t, acc);
    }

#pragma unroll
    for (int mt = 0; mt < 2; mt++) {
        int row0 = blockIdx.x * 128 + wm * 32 + mt * 16;
#pragma unroll
        for (int nt = 0; nt < 8; nt++) {
            int col = wn * 64 + nt * 8 + t * 2;
            *(float2*)(out + (long)(row0 + g) * 256 + col) =
                make_float2(fmaxf(acc[mt][nt][0], 0.0f), fmaxf(acc[mt][nt][1], 0.0f));
            *(float2*)(out + (long)(row0 + g + 8) * 256 + col) =
                make_float2(fmaxf(acc[mt][nt][2], 0.0f), fmaxf(acc[mt][nt][3], 0.0f));
        }
    }
}

extern "C" void kernel_launch(void* const* d_in, const int* in_sizes, int n_in,
                              void* d_out, int out_size) {
    const int*   node_ids = (const int*)d_in[0];
    const int*   nbr_ev   = (const int*)d_in[1];
    const int*   ev_st    = (const int*)d_in[2];
    const int*   ev_dt    = (const int*)d_in[3];
    const int*   ev_et    = (const int*)d_in[4];
    const int*   ev_sid   = (const int*)d_in[5];
    const int*   ev_did   = (const int*)d_in[6];
    const int*   ev_ts    = (const int*)d_in[7];
    const float* ev_w     = (const float*)d_in[8];
    const float* emb0     = (const float*)d_in[9];
    const float* emb1     = (const float*)d_in[10];
    const float* edge_emb = (const float*)d_in[11];
    const float* edge_lin = (const float*)d_in[12];
    const float* mlp_w1   = (const float*)d_in[13];
    const float* mlp_b1   = (const float*)d_in[14];
    const float* mlp_w2   = (const float*)d_in[15];
    const float* mlp_b2   = (const float*)d_in[16];
    const float* ev_src_w = (const float*)d_in[17];
    const float* ev_dst_w = (const float*)d_in[18];
    const float* self_w   = (const float*)d_in[19];
    const float* neigh_w  = (const float*)d_in[20];
    float* out = (float*)d_out;

    cudaFuncSetAttribute(k_events, cudaFuncAttributeMaxDynamicSharedMemorySize, SMEM_EV);
    cudaFuncSetAttribute(k_final,  cudaFuncAttributeMaxDynamicSharedMemorySize, SMEM_FI);

    k_prep<<<896, 256>>>(ev_src_w, ev_dst_w, mlp_w2, self_w, neigh_w);
    k_relproj<<<16, 256>>>(edge_emb, edge_lin, mlp_b2);
    k_events<<<BE / 128, 512, SMEM_EV>>>(nbr_ev, ev_st, ev_dt, ev_et, ev_sid, ev_did,
                                         ev_ts, ev_w, emb0, emb1, mlp_w1, mlp_b1);
    k_final<<<BN / 128, 512, SMEM_FI>>>(node_ids, emb0, out);
}